// round 6
// baseline (speedup 1.0000x reference)
#include <cuda_runtime.h>

#define BATCH 2048
#define TT    512
#define HID   64
#define GATES 256     // 4*HID
#define NB    14      // rows per CTA
#define NCTA  147     // ceil(2048/14) -> one balanced wave on 148 SMs
#define NTHR  512

typedef unsigned long long u64;

__device__ __forceinline__ u64 ffma2(u64 a, u64 b, u64 c) {
    u64 d;
    asm("fma.rn.f32x2 %0, %1, %2, %3;" : "=l"(d) : "l"(a), "l"(b), "l"(c));
    return d;
}

__device__ __forceinline__ float sum2(u64 v) {
    float lo, hi;
    asm("mov.b64 {%0, %1}, %2;" : "=f"(lo), "=f"(hi) : "l"(v));
    return lo + hi;
}

__device__ __forceinline__ float fast_sigmoid(float v) {
    return 1.0f / (1.0f + __expf(-v));
}

__device__ __forceinline__ float fast_tanh(float v) {
    float av = fabsf(v);
    float e  = __expf(-2.0f * av);
    float th = (1.0f - e) / (1.0f + e);
    return copysignf(th, v);
}

__global__ __launch_bounds__(NTHR, 1)
void lstm_kernel(const float* __restrict__ x,
                 const float* __restrict__ W_ih,
                 const float* __restrict__ W_hh,
                 const float* __restrict__ b_ih,
                 const float* __restrict__ b_hh,
                 const float* __restrict__ W_d,
                 const float* __restrict__ b_d,
                 float* __restrict__ out) {
    __shared__ float x_s[NB][TT];      // 28 KB
    __shared__ float h_s[NB][HID];     // 3.5 KB
    __shared__ float g_s[NB][GATES];   // 14 KB

    const int tid  = threadIdx.x;
    const int lane = tid & 31;
    const int warp = tid >> 5;
    const int kh   = lane >> 4;                    // k-half: 0 -> k[0,32), 1 -> k[32,64)
    const int cp   = ((warp & 7) << 4) | (lane & 15);  // column-pair id 0..127
    const int rg   = warp >> 3;                    // row group 0/1
    const int rbase = rg * 7;                      // rows rbase..rbase+6
    const int colA = cp;                           // i/f column (sigmoid)
    const int colB = cp + 128;                     // g/o column
    const int mycol = kh ? colB : colA;            // column this thread finalizes
    const bool isTanh = (kh == 1) && ((warp & 7) < 4);   // colB in g-range [128,192)

    const int row0 = blockIdx.x * NB;

    // --- per-thread weights: k-half of both owned columns (64 regs) ---
    u64 wA[16], wB[16];
    {
        const ulonglong2* pa = reinterpret_cast<const ulonglong2*>(W_hh + colA * HID + kh * 32);
        const ulonglong2* pb = reinterpret_cast<const ulonglong2*>(W_hh + colB * HID + kh * 32);
#pragma unroll
        for (int q = 0; q < 8; q++) {
            ulonglong2 va = pa[q];
            wA[2 * q + 0] = va.x;  wA[2 * q + 1] = va.y;
            ulonglong2 vb = pb[q];
            wB[2 * q + 0] = vb.x;  wB[2 * q + 1] = vb.y;
        }
    }
    const float bias = b_ih[mycol] + b_hh[mycol];
    const float wih  = W_ih[mycol];

    // --- stage x slab (coalesced along t; clamp rows past BATCH) ---
    for (int i = tid; i < NB * TT; i += NTHR) {
        int r = i >> 9;
        int t = i & (TT - 1);
        int gr = row0 + r;
        if (gr > BATCH - 1) gr = BATCH - 1;
        x_s[r][t] = x[gr * TT + t];
    }
    for (int i = tid; i < NB * HID; i += NTHR)
        ((float*)h_s)[i] = 0.0f;

    // --- phase-2 ownership: NB*HID = 896 cell states ---
    float c0 = 0.0f, c1 = 0.0f;
    const int r0a = tid >> 6,            m0 = tid & 63;
    const bool has1 = (tid < NB * HID - NTHR);   // tid < 384
    const int idx1 = tid + NTHR;
    const int r1a = idx1 >> 6,           m1 = idx1 & 63;

    __syncthreads();

    for (int t = 0; t < TT; t++) {
        // ---------- phase 1: partial dot products (k-half, both columns) ----------
        float pA[7], pB[7];
#pragma unroll
        for (int r = 0; r < 7; r++) {
            const int rr = rbase + r;
            u64 aA = 0ull, aB = 0ull;          // (0.0f, 0.0f)
#pragma unroll
            for (int half = 0; half < 2; half++) {
                ulonglong2 hv[4];
#pragma unroll
                for (int q = 0; q < 4; q++)    // 4 back-to-back LDS.128 (MLP=4)
                    hv[q] = *reinterpret_cast<const ulonglong2*>(
                        &h_s[rr][kh * 32 + half * 16 + q * 4]);
#pragma unroll
                for (int q = 0; q < 4; q++) {
                    int b = half * 8 + 2 * q;
                    aA = ffma2(wA[b + 0], hv[q].x, aA);
                    aA = ffma2(wA[b + 1], hv[q].y, aA);
                    aB = ffma2(wB[b + 0], hv[q].x, aB);
                    aB = ffma2(wB[b + 1], hv[q].y, aB);
                }
            }
            pA[r] = sum2(aA);
            pB[r] = sum2(aB);
        }

        // ---------- reduce across k-half partner (lane ^ 16), convergent ----------
        float tot[7];
#pragma unroll
        for (int r = 0; r < 7; r++) {
            float send = kh ? pA[r] : pB[r];
            float recv = __shfl_xor_sync(0xffffffffu, send, 16);
            float own  = kh ? pB[r] : pA[r];
            const int rr = rbase + r;
            tot[r] = fmaf(x_s[rr][t], wih, bias) + own + recv;
        }

        // ---------- activation + store (half-warp divergent, shfl already done) ----
        if (isTanh) {
#pragma unroll
            for (int r = 0; r < 7; r++) g_s[rbase + r][mycol] = fast_tanh(tot[r]);
        } else {
#pragma unroll
            for (int r = 0; r < 7; r++) g_s[rbase + r][mycol] = fast_sigmoid(tot[r]);
        }
        __syncthreads();

        // ---------- phase 2: cell/hidden update ----------
        {
            float i_ = g_s[r0a][m0];
            float f_ = g_s[r0a][64 + m0];
            float gg = g_s[r0a][128 + m0];
            float o_ = g_s[r0a][192 + m0];
            c0 = fmaf(f_, c0, i_ * gg);
            h_s[r0a][m0] = o_ * fast_tanh(c0);
        }
        if (has1) {
            float i_ = g_s[r1a][m1];
            float f_ = g_s[r1a][64 + m1];
            float gg = g_s[r1a][128 + m1];
            float o_ = g_s[r1a][192 + m1];
            c1 = fmaf(f_, c1, i_ * gg);
            h_s[r1a][m1] = o_ * fast_tanh(c1);
        }
        __syncthreads();
    }

    // ---------- final projection ----------
    if (tid < NB && row0 + tid < BATCH) {
        float s = b_d[0];
#pragma unroll
        for (int m = 0; m < HID; m++)
            s = fmaf(h_s[tid][m], W_d[m], s);
        out[row0 + tid] = s;
    }
}

extern "C" void kernel_launch(void* const* d_in, const int* in_sizes, int n_in,
                              void* d_out, int out_size) {
    const float* x    = (const float*)d_in[0];
    const float* W_ih = (const float*)d_in[1];
    const float* W_hh = (const float*)d_in[2];
    const float* b_ih = (const float*)d_in[3];
    const float* b_hh = (const float*)d_in[4];
    const float* W_d  = (const float*)d_in[5];
    const float* b_d  = (const float*)d_in[6];
    float* out = (float*)d_out;

    lstm_kernel<<<NCTA, NTHR>>>(x, W_ih, W_hh, b_ih, b_hh, W_d, b_d, out);
}

// round 7
// speedup vs baseline: 1.0192x; 1.0192x over previous
#include <cuda_runtime.h>

#define BATCH 2048
#define TT    512
#define HID   64
#define GATES 256     // 4*HID
#define NB    7       // rows per CTA (296 CTAs = exactly 2 per SM)
#define NCTA  296
#define NTHR  256

typedef unsigned long long u64;

__device__ __forceinline__ u64 ffma2(u64 a, u64 b, u64 c) {
    u64 d;
    asm("fma.rn.f32x2 %0, %1, %2, %3;" : "=l"(d) : "l"(a), "l"(b), "l"(c));
    return d;
}

__device__ __forceinline__ float sum2(u64 v) {
    float lo, hi;
    asm("mov.b64 {%0, %1}, %2;" : "=f"(lo), "=f"(hi) : "l"(v));
    return lo + hi;
}

__device__ __forceinline__ float fast_sigmoid(float v) {
    return 1.0f / (1.0f + __expf(-v));
}

__device__ __forceinline__ float fast_tanh(float v) {
    float av = fabsf(v);
    float e  = __expf(-2.0f * av);
    float th = (1.0f - e) / (1.0f + e);
    return copysignf(th, v);
}

__global__ __launch_bounds__(NTHR, 2)
void lstm_kernel(const float* __restrict__ x,
                 const float* __restrict__ W_ih,
                 const float* __restrict__ W_hh,
                 const float* __restrict__ b_ih,
                 const float* __restrict__ b_hh,
                 const float* __restrict__ W_d,
                 const float* __restrict__ b_d,
                 float* __restrict__ out) {
    __shared__ float x_s[NB][TT];      // 14 KB
    __shared__ float h_s[NB][HID];     // 1.75 KB
    __shared__ float g_s[NB][GATES];   // 7 KB

    const int tid  = threadIdx.x;
    const int lane = tid & 31;
    const int warp = tid >> 5;                    // 0..7
    const int kh   = lane >> 4;                   // k-half: 0 -> k[0,32), 1 -> k[32,64)
    const int cp   = (warp << 4) | (lane & 15);   // column-pair id 0..127
    const int colA = cp;                          // i/f column (always sigmoid)
    const int colB = cp + 128;                    // g/o column
    const int mycol = kh ? colB : colA;           // column this thread finalizes
    const bool isTanh = (kh == 1) && (warp < 4);  // colB in g-range [128,192)

    const int row0 = blockIdx.x * NB;

    // --- per-thread weights: k-half of both owned columns (64 regs total) ---
    u64 wA[16], wB[16];
    {
        const ulonglong2* pa = reinterpret_cast<const ulonglong2*>(W_hh + colA * HID + kh * 32);
        const ulonglong2* pb = reinterpret_cast<const ulonglong2*>(W_hh + colB * HID + kh * 32);
#pragma unroll
        for (int q = 0; q < 8; q++) {
            ulonglong2 va = pa[q];
            wA[2 * q + 0] = va.x;  wA[2 * q + 1] = va.y;
            ulonglong2 vb = pb[q];
            wB[2 * q + 0] = vb.x;  wB[2 * q + 1] = vb.y;
        }
    }
    const float bias = b_ih[mycol] + b_hh[mycol];
    const float wih  = W_ih[mycol];

    // --- stage x slab (coalesced; clamp rows past BATCH) ---
    for (int i = tid; i < NB * TT; i += NTHR) {
        int r = i / TT;
        int t = i % TT;
        int gr = row0 + r;
        if (gr > BATCH - 1) gr = BATCH - 1;
        x_s[r][t] = x[gr * TT + t];
    }
    for (int i = tid; i < NB * HID; i += NTHR)
        ((float*)h_s)[i] = 0.0f;

    // --- phase-2 ownership: NB*HID = 448 cell states ---
    float c0 = 0.0f, c1 = 0.0f;
    const int r0a = tid >> 6,            m0 = tid & 63;
    const bool has1 = (tid < NB * HID - NTHR);   // tid < 192
    const int idx1 = tid + NTHR;
    const int r1a = idx1 >> 6,           m1 = idx1 & 63;

    __syncthreads();

    for (int t = 0; t < TT; t++) {
        // ---------- phase 1: k-half partial dots for both columns, all 7 rows ----
        float pA[NB], pB[NB];
#pragma unroll
        for (int r = 0; r < NB; r++) {
            u64 aA = 0ull, aB = 0ull;
#pragma unroll
            for (int half = 0; half < 2; half++) {
                ulonglong2 hv[4];
#pragma unroll
                for (int q = 0; q < 4; q++)     // 4 back-to-back LDS.128 (MLP=4)
                    hv[q] = *reinterpret_cast<const ulonglong2*>(
                        &h_s[r][kh * 32 + half * 16 + q * 4]);
#pragma unroll
                for (int q = 0; q < 4; q++) {
                    int b = half * 8 + 2 * q;
                    aA = ffma2(wA[b + 0], hv[q].x, aA);
                    aA = ffma2(wA[b + 1], hv[q].y, aA);
                    aB = ffma2(wB[b + 0], hv[q].x, aB);
                    aB = ffma2(wB[b + 1], hv[q].y, aB);
                }
            }
            pA[r] = sum2(aA);
            pB[r] = sum2(aB);
        }

        // ---------- reduce across k-half partner (lane ^ 16), convergent ----------
        float tot[NB];
#pragma unroll
        for (int r = 0; r < NB; r++) {
            float send = kh ? pA[r] : pB[r];
            float recv = __shfl_xor_sync(0xffffffffu, send, 16);
            float own  = kh ? pB[r] : pA[r];
            tot[r] = fmaf(x_s[r][t], wih, bias) + own + recv;
        }

        // ---------- activation + store (half-warp divergence on small branch) ----
        if (isTanh) {
#pragma unroll
            for (int r = 0; r < NB; r++) g_s[r][mycol] = fast_tanh(tot[r]);
        } else {
#pragma unroll
            for (int r = 0; r < NB; r++) g_s[r][mycol] = fast_sigmoid(tot[r]);
        }
        __syncthreads();

        // ---------- phase 2: cell/hidden update ----------
        {
            float i_ = g_s[r0a][m0];
            float f_ = g_s[r0a][64 + m0];
            float gg = g_s[r0a][128 + m0];
            float o_ = g_s[r0a][192 + m0];
            c0 = fmaf(f_, c0, i_ * gg);
            h_s[r0a][m0] = o_ * fast_tanh(c0);
        }
        if (has1) {
            float i_ = g_s[r1a][m1];
            float f_ = g_s[r1a][64 + m1];
            float gg = g_s[r1a][128 + m1];
            float o_ = g_s[r1a][192 + m1];
            c1 = fmaf(f_, c1, i_ * gg);
            h_s[r1a][m1] = o_ * fast_tanh(c1);
        }
        __syncthreads();
    }

    // ---------- final projection ----------
    if (tid < NB && row0 + tid < BATCH) {
        float s = b_d[0];
#pragma unroll
        for (int m = 0; m < HID; m++)
            s = fmaf(h_s[tid][m], W_d[m], s);
        out[row0 + tid] = s;
    }
}

extern "C" void kernel_launch(void* const* d_in, const int* in_sizes, int n_in,
                              void* d_out, int out_size) {
    const float* x    = (const float*)d_in[0];
    const float* W_ih = (const float*)d_in[1];
    const float* W_hh = (const float*)d_in[2];
    const float* b_ih = (const float*)d_in[3];
    const float* b_hh = (const float*)d_in[4];
    const float* W_d  = (const float*)d_in[5];
    const float* b_d  = (const float*)d_in[6];
    float* out = (float*)d_out;

    lstm_kernel<<<NCTA, NTHR>>>(x, W_ih, W_hh, b_ih, b_hh, W_d, b_d, out);
}

// round 8
// speedup vs baseline: 1.4937x; 1.4656x over previous
#include <cuda_runtime.h>

#define BATCH 2048
#define TT    512
#define HID   64
#define GATES 256     // 4*HID
#define NB    7       // rows per CTA (296 CTAs = exactly 2 per SM)
#define NCTA  296
#define NTHR  256

typedef unsigned long long u64;

__device__ __forceinline__ u64 ffma2(u64 a, u64 b, u64 c) {
    u64 d;
    asm("fma.rn.f32x2 %0, %1, %2, %3;" : "=l"(d) : "l"(a), "l"(b), "l"(c));
    return d;
}

__device__ __forceinline__ float sum2(u64 v) {
    float lo, hi;
    asm("mov.b64 {%0, %1}, %2;" : "=f"(lo), "=f"(hi) : "l"(v));
    return lo + hi;
}

__device__ __forceinline__ float tanh_fast(float v) {
    float r;
    asm("tanh.approx.f32 %0, %1;" : "=f"(r) : "f"(v));
    return r;
}

__global__ __launch_bounds__(NTHR, 2)
void lstm_kernel(const float* __restrict__ x,
                 const float* __restrict__ W_ih,
                 const float* __restrict__ W_hh,
                 const float* __restrict__ b_ih,
                 const float* __restrict__ b_hh,
                 const float* __restrict__ W_d,
                 const float* __restrict__ b_d,
                 float* __restrict__ out) {
    __shared__ float x_s[NB][TT];      // 14 KB
    __shared__ float h_s[NB][HID];     // 1.75 KB
    __shared__ float g_s[NB][GATES];   // 7 KB

    const int tid  = threadIdx.x;
    const int lane = tid & 31;
    const int warp = tid >> 5;                    // 0..7
    const int kh   = lane >> 4;                   // k-half: 0 -> k[0,32), 1 -> k[32,64)
    const int cp   = (warp << 4) | (lane & 15);   // column-pair id 0..127
    const int colA = cp;                          // i/f column (always sigmoid)
    const int colB = cp + 128;                    // g/o column
    const int mycol = kh ? colB : colA;           // column this thread finalizes
    const bool isTanh = (kh == 1) && (warp < 4);  // colB in g-range [128,192)
    // branchless activation params: act(v) = s0 + s1*tanh(sc*v)
    const float s0 = isTanh ? 0.0f : 0.5f;
    const float s1 = isTanh ? 1.0f : 0.5f;
    const float sc = isTanh ? 1.0f : 0.5f;

    const int row0 = blockIdx.x * NB;

    // --- per-thread weights: k-half of both owned columns (64 regs total) ---
    u64 wA[16], wB[16];
    {
        const ulonglong2* pa = reinterpret_cast<const ulonglong2*>(W_hh + colA * HID + kh * 32);
        const ulonglong2* pb = reinterpret_cast<const ulonglong2*>(W_hh + colB * HID + kh * 32);
#pragma unroll
        for (int q = 0; q < 8; q++) {
            ulonglong2 va = pa[q];
            wA[2 * q + 0] = va.x;  wA[2 * q + 1] = va.y;
            ulonglong2 vb = pb[q];
            wB[2 * q + 0] = vb.x;  wB[2 * q + 1] = vb.y;
        }
    }
    const float bias = b_ih[mycol] + b_hh[mycol];
    const float wih  = W_ih[mycol];
    const int khoff  = kh * 32;

    // --- stage x slab (coalesced; clamp rows past BATCH) ---
    for (int i = tid; i < NB * TT; i += NTHR) {
        int r = i / TT;
        int t = i % TT;
        int gr = row0 + r;
        if (gr > BATCH - 1) gr = BATCH - 1;
        x_s[r][t] = x[gr * TT + t];
    }
    for (int i = tid; i < NB * HID; i += NTHR)
        ((float*)h_s)[i] = 0.0f;

    // --- phase-2 ownership: NB*HID = 448 cell states ---
    float c0 = 0.0f, c1 = 0.0f;
    const int r0a = tid >> 6,            m0 = tid & 63;
    const bool has1 = (tid < NB * HID - NTHR);   // tid < 192
    const int idx1 = tid + NTHR;
    const int r1a = idx1 >> 6,           m1 = idx1 & 63;

    __syncthreads();

    for (int t = 0; t < TT; t++) {
        // hoisted x loads for all rows (broadcast, MLP batch)
        float xv[NB];
#pragma unroll
        for (int r = 0; r < NB; r++) xv[r] = x_s[r][t];

        // ---------- phase 1: software-pipelined over rows ----------
        ulonglong2 hva[4], hvb[4];
#pragma unroll
        for (int q = 0; q < 4; q++)        // prologue: row 0, half 0
            hva[q] = *reinterpret_cast<const ulonglong2*>(&h_s[0][khoff + q * 4]);

#pragma unroll
        for (int r = 0; r < NB; r++) {
            // load half 1 of row r
#pragma unroll
            for (int q = 0; q < 4; q++)
                hvb[q] = *reinterpret_cast<const ulonglong2*>(&h_s[r][khoff + 16 + q * 4]);

            u64 aA = 0ull, aB = 0ull;
            // consume half 0
#pragma unroll
            for (int q = 0; q < 4; q++) {
                aA = ffma2(wA[2 * q + 0], hva[q].x, aA);
                aA = ffma2(wA[2 * q + 1], hva[q].y, aA);
                aB = ffma2(wB[2 * q + 0], hva[q].x, aB);
                aB = ffma2(wB[2 * q + 1], hva[q].y, aB);
            }
            // prefetch half 0 of row r+1 (overlaps half-1 FMAs below)
            if (r + 1 < NB) {
#pragma unroll
                for (int q = 0; q < 4; q++)
                    hva[q] = *reinterpret_cast<const ulonglong2*>(&h_s[r + 1][khoff + q * 4]);
            }
            // consume half 1
#pragma unroll
            for (int q = 0; q < 4; q++) {
                aA = ffma2(wA[8 + 2 * q + 0], hvb[q].x, aA);
                aA = ffma2(wA[8 + 2 * q + 1], hvb[q].y, aA);
                aB = ffma2(wB[8 + 2 * q + 0], hvb[q].x, aB);
                aB = ffma2(wB[8 + 2 * q + 1], hvb[q].y, aB);
            }

            // reduce across k-half partner (lane ^ 16), convergent; per-row so
            // the SHFL/MUFU tail overlaps the next row's loads/FMAs
            float pA = sum2(aA), pB = sum2(aB);
            float send = kh ? pA : pB;
            float recv = __shfl_xor_sync(0xffffffffu, send, 16);
            float own  = kh ? pB : pA;
            float tot  = fmaf(xv[r], wih, bias) + own + recv;
            g_s[r][mycol] = fmaf(s1, tanh_fast(sc * tot), s0);
        }
        __syncthreads();

        // ---------- phase 2: cell/hidden update ----------
        {
            float i_ = g_s[r0a][m0];
            float f_ = g_s[r0a][64 + m0];
            float gg = g_s[r0a][128 + m0];
            float o_ = g_s[r0a][192 + m0];
            c0 = fmaf(f_, c0, i_ * gg);
            h_s[r0a][m0] = o_ * tanh_fast(c0);
        }
        if (has1) {
            float i_ = g_s[r1a][m1];
            float f_ = g_s[r1a][64 + m1];
            float gg = g_s[r1a][128 + m1];
            float o_ = g_s[r1a][192 + m1];
            c1 = fmaf(f_, c1, i_ * gg);
            h_s[r1a][m1] = o_ * tanh_fast(c1);
        }
        __syncthreads();
    }

    // ---------- final projection ----------
    if (tid < NB && row0 + tid < BATCH) {
        float s = b_d[0];
#pragma unroll
        for (int m = 0; m < HID; m++)
            s = fmaf(h_s[tid][m], W_d[m], s);
        out[row0 + tid] = s;
    }
}

extern "C" void kernel_launch(void* const* d_in, const int* in_sizes, int n_in,
                              void* d_out, int out_size) {
    const float* x    = (const float*)d_in[0];
    const float* W_ih = (const float*)d_in[1];
    const float* W_hh = (const float*)d_in[2];
    const float* b_ih = (const float*)d_in[3];
    const float* b_hh = (const float*)d_in[4];
    const float* W_d  = (const float*)d_in[5];
    const float* b_d  = (const float*)d_in[6];
    float* out = (float*)d_out;

    lstm_kernel<<<NCTA, NTHR>>>(x, W_ih, W_hh, b_ih, b_hh, W_d, b_d, out);
}